// round 4
// baseline (speedup 1.0000x reference)
#include <cuda_runtime.h>

// y[..., 2k]   = T[k,0,0]*x[2k] + T[k,0,1]*x[2k+1]
// y[..., 2k+1] = T[k,1,0]*x[2k] + T[k,1,1]*x[2k+1]
// x: (4, 2048, 4096) fp32 (128 MiB), twiddle: (2048, 2, 2) fp32 (32 KiB).
//
// sm_103a: L2 evict hints require 256-bit accesses (.v8.b32). Each thread
// handles 8 consecutive floats (4 pairs) per step via one LDG.256 + two
// twiddle LDG.256 + one STG.256. x/tw pinned via evict_last (graph replays
// reread the same x -> make it L2-resident); y stores evict_first so the
// write stream doesn't flush x.

struct f8 { float v[8]; };

__device__ __forceinline__ f8 ldg256_evict_last(const float* p) {
    f8 r;
    asm volatile("ld.global.nc.L2::evict_last.v8.b32 "
                 "{%0,%1,%2,%3,%4,%5,%6,%7}, [%8];"
                 : "=f"(r.v[0]), "=f"(r.v[1]), "=f"(r.v[2]), "=f"(r.v[3]),
                   "=f"(r.v[4]), "=f"(r.v[5]), "=f"(r.v[6]), "=f"(r.v[7])
                 : "l"(p));
    return r;
}

__device__ __forceinline__ void stg256_evict_first(float* p, const f8& r) {
    asm volatile("st.global.L2::evict_first.v8.b32 "
                 "[%0], {%1,%2,%3,%4,%5,%6,%7,%8};"
                 :: "l"(p),
                    "f"(r.v[0]), "f"(r.v[1]), "f"(r.v[2]), "f"(r.v[3]),
                    "f"(r.v[4]), "f"(r.v[5]), "f"(r.v[6]), "f"(r.v[7])
                 : "memory");
}

__global__ __launch_bounds__(256) void butterfly_kernel(
    const float* __restrict__ x,
    const float* __restrict__ tw,    // tw[k] = (t00, t01, t10, t11), 16B each
    float* __restrict__ y)
{
    const int t        = threadIdx.x;
    const int row_base = blockIdx.x << 12;        // row * 4096 floats

    f8 v[2], ta[2], tb[2];

    // Front-batch all independent 256-bit loads for deep MLP.
#pragma unroll
    for (int u = 0; u < 2; u++) {
        const int c = t + (u << 8);               // chunk index within row
        v[u] = ldg256_evict_last(&x[row_base + (c << 3)]);
    }
#pragma unroll
    for (int u = 0; u < 2; u++) {
        const int c = t + (u << 8);
        // chunk covers pairs [4c, 4c+3] -> twiddle floats [16c, 16c+16)
        ta[u] = ldg256_evict_last(&tw[c << 4]);
        tb[u] = ldg256_evict_last(&tw[(c << 4) + 8]);
    }

#pragma unroll
    for (int u = 0; u < 2; u++) {
        const int c = t + (u << 8);
        f8 r;
        // pairs 0,1 use ta[u] (twiddles 4c, 4c+1), pairs 2,3 use tb[u]
        r.v[0] = fmaf(ta[u].v[0], v[u].v[0], ta[u].v[1] * v[u].v[1]);
        r.v[1] = fmaf(ta[u].v[2], v[u].v[0], ta[u].v[3] * v[u].v[1]);
        r.v[2] = fmaf(ta[u].v[4], v[u].v[2], ta[u].v[5] * v[u].v[3]);
        r.v[3] = fmaf(ta[u].v[6], v[u].v[2], ta[u].v[7] * v[u].v[3]);
        r.v[4] = fmaf(tb[u].v[0], v[u].v[4], tb[u].v[1] * v[u].v[5]);
        r.v[5] = fmaf(tb[u].v[2], v[u].v[4], tb[u].v[3] * v[u].v[5]);
        r.v[6] = fmaf(tb[u].v[4], v[u].v[6], tb[u].v[5] * v[u].v[7]);
        r.v[7] = fmaf(tb[u].v[6], v[u].v[6], tb[u].v[7] * v[u].v[7]);
        stg256_evict_first(&y[row_base + (c << 3)], r);
    }
}

extern "C" void kernel_launch(void* const* d_in, const int* in_sizes, int n_in,
                              void* d_out, int out_size)
{
    const float* x  = (const float*)d_in[0];
    const float* tw = (const float*)d_in[1];
    float* y        = (float*)d_out;

    const int rows = out_size >> 12;   // 4096 floats per row -> 8192 blocks

    butterfly_kernel<<<rows, 256>>>(x, tw, y);
}